// round 3
// baseline (speedup 1.0000x reference)
#include <cuda_runtime.h>

// Diffusion_38929583571393: 10 iterations of x += 0.05 * (grad_x + grad_y + grad_z)
// on a (64, 1024, 1024) fp32 volume, torch.gradient semantics.
//
// R3 change vs R2: prefetch pipeline depth 1 -> 3 along the x-march.
// R2 ncu showed DRAM=46%, 3.67 TB/s == latency-limited (1 cold load in
// flight per warp, ~38 warps/SM). Depth-3 prefetch triples cold-load MLP.

#define NX 64
#define NY 1024
#define NZ 1024
#define SX (NY * NZ)   // x stride = 1048576 elems
#define SY (NZ)        // y stride = 1024 elems
#define COEFF 0.05f    // ALPHA * DT
#define NITER 10

// Ping-pong scratch (allocation-free per harness rules): 256 MB bss.
__device__ float g_scratch[(size_t)NX * NY * NZ];

__device__ __forceinline__ float4 ld4(const float* __restrict__ p) {
    return *reinterpret_cast<const float4*>(p);
}
__device__ __forceinline__ void st4(float* __restrict__ p, float4 v) {
    *reinterpret_cast<float4*>(p) = v;
}

// Tile: y = 8 rows, z = 128 floats (32 lanes * float4). Block marches x,
// keeping planes x-1 / x / x+1..x+3 in registers. The streamed plane load is
// the only cold DRAM read; y/z neighbors hit L1/L2 (4 MB plane << 126 MB L2).
__global__ __launch_bounds__(256, 5) void diff_step(const float* __restrict__ in,
                                                    float* __restrict__ out) {
    const int z = (blockIdx.x * 32 + threadIdx.x) << 2;       // 0..1020, step 4
    const int y = blockIdx.y * 8 + threadIdx.y;               // 0..1023
    const unsigned base = (unsigned)y * SY + (unsigned)z;

    const bool y_lo = (y == 0);
    const bool y_hi = (y == NY - 1);
    const bool z_lo = (z == 0);
    const bool z_hi = (z + 4 == NZ);

    const float* __restrict__ pin = in + base;
    float* __restrict__ pout = out + base;

    // Pipeline: cc = plane x, p1/p2/p3 = planes x+1 / x+2 / x+3.
    float4 cc = ld4(pin);
    float4 p1 = ld4(pin + 1 * SX);
    float4 p2 = ld4(pin + 2 * SX);
    float4 p3 = ld4(pin + 3 * SX);
    float4 cm = cc;                   // dummy until x >= 1

    #pragma unroll 1
    for (int x = 0; x < NX; ++x) {
        const float4 cp = p1;        // plane x+1 (clamped dup at x=63; unused)

        // ---- grad_x (axis 0, size 64) ----
        float4 gx;
        if (x == 0) {
            gx.x = cp.x - cc.x; gx.y = cp.y - cc.y;
            gx.z = cp.z - cc.z; gx.w = cp.w - cc.w;
        } else if (x == NX - 1) {
            gx.x = cc.x - cm.x; gx.y = cc.y - cm.y;
            gx.z = cc.z - cm.z; gx.w = cc.w - cm.w;
        } else {
            gx.x = 0.5f * (cp.x - cm.x); gx.y = 0.5f * (cp.y - cm.y);
            gx.z = 0.5f * (cp.z - cm.z); gx.w = 0.5f * (cp.w - cm.w);
        }

        // ---- grad_y (axis 1, size 1024) ----
        float4 gy;
        if (y_lo) {
            float4 yp = ld4(pin + SY);
            gy.x = yp.x - cc.x; gy.y = yp.y - cc.y;
            gy.z = yp.z - cc.z; gy.w = yp.w - cc.w;
        } else if (y_hi) {
            float4 ym = ld4(pin - SY);
            gy.x = cc.x - ym.x; gy.y = cc.y - ym.y;
            gy.z = cc.z - ym.z; gy.w = cc.w - ym.w;
        } else {
            float4 ym = ld4(pin - SY);
            float4 yp = ld4(pin + SY);
            gy.x = 0.5f * (yp.x - ym.x); gy.y = 0.5f * (yp.y - ym.y);
            gy.z = 0.5f * (yp.z - ym.z); gy.w = 0.5f * (yp.w - ym.w);
        }

        // ---- grad_z (axis 2, size 1024, contiguous) ----
        float zl = z_lo ? 0.0f : pin[-1];
        float zr = z_hi ? 0.0f : pin[4];
        float4 gz;
        gz.x = z_lo ? (cc.y - cc.x) : 0.5f * (cc.y - zl);
        gz.y = 0.5f * (cc.z - cc.x);
        gz.z = 0.5f * (cc.w - cc.y);
        gz.w = z_hi ? (cc.w - cc.z) : 0.5f * (zr - cc.z);

        float4 o;
        o.x = fmaf(COEFF, gx.x + gy.x + gz.x, cc.x);
        o.y = fmaf(COEFF, gx.y + gy.y + gz.y, cc.y);
        o.z = fmaf(COEFF, gx.z + gy.z + gz.z, cc.z);
        o.w = fmaf(COEFF, gx.w + gy.w + gz.w, cc.w);
        st4(pout, o);

        // rotate the pipeline, stream plane x+4 (clamped; dup loads of the
        // last plane are L1 hits and their values are never consumed)
        cm = cc;
        cc = p1;
        p1 = p2;
        p2 = p3;
        const int xn = (x + 4 < NX) ? (x + 4) : (NX - 1);
        p3 = ld4(in + base + (unsigned)xn * SX);

        pin += SX;
        pout += SX;
    }
}

extern "C" void kernel_launch(void* const* d_in, const int* in_sizes, int n_in,
                              void* d_out, int out_size) {
    const float* x = (const float*)d_in[0];
    float* out = (float*)d_out;
    float* scratch = nullptr;
    cudaGetSymbolAddress((void**)&scratch, g_scratch);

    dim3 block(32, 8);
    dim3 grid(NZ / 128, NY / 8);   // 8 x 128 = 1024 blocks

    const float* src = x;
    for (int it = 0; it < NITER; ++it) {
        // even iters write scratch, odd write out -> iter 9 lands in d_out
        float* dst = (it & 1) ? out : scratch;
        diff_step<<<grid, block>>>(src, dst);
        src = dst;
    }
}

// round 5
// speedup vs baseline: 1.4142x; 1.4142x over previous
#include <cuda_runtime.h>
#include <cstdint>

// Diffusion_38929583571393: 10 iters of x += 0.05*(grad_x+grad_y+grad_z) on a
// (64,1024,1024) fp32 volume, torch.gradient semantics.
//
// R4/R5: cp.async staged-smem pipeline. R2/R3 ncu showed ~3.5 TB/s / 44-46%
// DRAM = latency-bound: the y-neighbor gmem loads sit in the per-iteration
// dependency chain. Now each block streams halo'd plane tiles (10 rows x 136
// floats) into an 8-stage smem ring via cp.async.cg, 6 planes deep; all
// stencil reads become 29-cyc LDS and the gmem stream is fully asynchronous.

#define NX 64
#define NY 1024
#define NZ 1024
#define SX (NY * NZ)
#define SY (NZ)
#define COEFF 0.05f
#define NITER 10

#define S 8            // ring stages
#define ROWP 136       // floats per staged row (z0-4 .. z0+131)
#define STAGE_F (10 * ROWP)   // 10 rows (y0-1 .. y0+8)
#define NOPS 340       // 10 rows * 34 x 16B chunks per stage

__device__ float g_scratch[(size_t)NX * NY * NZ];

__device__ __forceinline__ void cpa16(uint32_t s, const float* __restrict__ g) {
    asm volatile("cp.async.cg.shared.global [%0], [%1], 16;" :: "r"(s), "l"(g));
}
__device__ __forceinline__ void cp_commit() {
    asm volatile("cp.async.commit_group;" ::: "memory");
}
__device__ __forceinline__ void cp_wait4() {
    asm volatile("cp.async.wait_group 4;" ::: "memory");
}

__global__ __launch_bounds__(256, 5) void diff_step(const float* __restrict__ in,
                                                    float* __restrict__ out) {
    __shared__ float st[S * STAGE_F];   // 43520 B

    const int tx = threadIdx.x;         // 0..31, z direction (float4)
    const int ty = threadIdx.y;         // 0..7,  y direction
    const int tid = ty * 32 + tx;
    const int z0 = blockIdx.x * 128;
    const int y0 = blockIdx.y * 8;

    const bool y_lo = (y0 == 0 && ty == 0);
    const bool y_hi = (y0 + 8 == NY && ty == 7);
    const bool z_lo = (z0 == 0 && tx == 0);
    const bool z_hi = (z0 + 128 == NZ && tx == 31);

    // Stage-fill op map: op o -> row o/34, chunk o%34. Threads 0..83 do two
    // ops. Out-of-range halo addresses are CLAMPED (loaded but never read by
    // the boundary branches), keeping every cp.async unpredicated & in-bounds.
    int g0, s0, g1 = -1, s1 = 0;
    {
        int o = tid;
        int ro = o / 34, co = o - ro * 34;
        int gy = min(max(y0 - 1 + ro, 0), NY - 1);
        int gz = min(max(z0 - 4 + 4 * co, 0), NZ - 4);
        g0 = gy * SY + gz;
        s0 = ro * ROWP + 4 * co;
        o = tid + 256;
        if (o < NOPS) {
            ro = o / 34; co = o - ro * 34;
            gy = min(max(y0 - 1 + ro, 0), NY - 1);
            gz = min(max(z0 - 4 + 4 * co, 0), NZ - 4);
            g1 = gy * SY + gz;
            s1 = ro * ROWP + 4 * co;
        }
    }

    const uint32_t sb = (uint32_t)__cvta_generic_to_shared(st);

    // Prologue: issue planes 0..S-3 (6 groups in flight).
    #pragma unroll
    for (int p = 0; p < S - 2; ++p) {
        const uint32_t sl = sb + (uint32_t)(p * STAGE_F * 4);
        const float* gp = in + (size_t)p * SX;
        cpa16(sl + (uint32_t)s0 * 4, gp + g0);
        if (g1 >= 0) cpa16(sl + (uint32_t)s1 * 4, gp + g1);
        cp_commit();
    }

    const int coff = (1 + ty) * ROWP + 4 + 4 * tx;   // center offset in a stage
    const unsigned obase = (unsigned)(y0 + ty) * SY + (unsigned)(z0 + 4 * tx);

    #pragma unroll 1
    for (int x = 0; x < NX; ++x) {
        cp_wait4();            // planes <= x+1 complete (<=4 groups pending)
        __syncthreads();       // make all threads' staged data visible

        const float* sc = st + (x & 7) * STAGE_F + coff;
        const float4 cc = *(const float4*)sc;
        const float4 ym = *(const float4*)(sc - ROWP);
        const float4 yp = *(const float4*)(sc + ROWP);
        const float zl = sc[-1];
        const float zr = sc[4];
        const float4 cm = *(const float4*)(st + ((x + 7) & 7) * STAGE_F + coff);
        const float4 cp = *(const float4*)(st + ((x + 1) & 7) * STAGE_F + coff);

        // ---- grad_x (axis 0) ----
        float4 gx;
        if (x == 0) {
            gx.x = cp.x - cc.x; gx.y = cp.y - cc.y;
            gx.z = cp.z - cc.z; gx.w = cp.w - cc.w;
        } else if (x == NX - 1) {
            gx.x = cc.x - cm.x; gx.y = cc.y - cm.y;
            gx.z = cc.z - cm.z; gx.w = cc.w - cm.w;
        } else {
            gx.x = 0.5f * (cp.x - cm.x); gx.y = 0.5f * (cp.y - cm.y);
            gx.z = 0.5f * (cp.z - cm.z); gx.w = 0.5f * (cp.w - cm.w);
        }

        // ---- grad_y (axis 1) ----
        float4 gy;
        if (y_lo) {
            gy.x = yp.x - cc.x; gy.y = yp.y - cc.y;
            gy.z = yp.z - cc.z; gy.w = yp.w - cc.w;
        } else if (y_hi) {
            gy.x = cc.x - ym.x; gy.y = cc.y - ym.y;
            gy.z = cc.z - ym.z; gy.w = cc.w - ym.w;
        } else {
            gy.x = 0.5f * (yp.x - ym.x); gy.y = 0.5f * (yp.y - ym.y);
            gy.z = 0.5f * (yp.z - ym.z); gy.w = 0.5f * (yp.w - ym.w);
        }

        // ---- grad_z (axis 2, contiguous) ----
        float4 gz;
        gz.x = z_lo ? (cc.y - cc.x) : 0.5f * (cc.y - zl);
        gz.y = 0.5f * (cc.z - cc.x);
        gz.z = 0.5f * (cc.w - cc.y);
        gz.w = z_hi ? (cc.w - cc.z) : 0.5f * (zr - cc.z);

        float4 o;
        o.x = fmaf(COEFF, gx.x + gy.x + gz.x, cc.x);
        o.y = fmaf(COEFF, gx.y + gy.y + gz.y, cc.y);
        o.z = fmaf(COEFF, gx.z + gy.z + gz.z, cc.z);
        o.w = fmaf(COEFF, gx.w + gy.w + gz.w, cc.w);
        *reinterpret_cast<float4*>(out + (size_t)x * SX + obase) = o;

        // Prefetch plane x+6 into slot (x+6)&7 (overwrites plane x-2, whose
        // last reader finished before this iteration's __syncthreads).
        const int p = x + S - 2;
        if (p < NX) {
            const uint32_t sl = sb + (uint32_t)((p & 7) * STAGE_F * 4);
            const float* gp = in + (size_t)p * SX;
            cpa16(sl + (uint32_t)s0 * 4, gp + g0);
            if (g1 >= 0) cpa16(sl + (uint32_t)s1 * 4, gp + g1);
        }
        cp_commit();   // commit even when empty to keep group arithmetic fixed
    }
}

extern "C" void kernel_launch(void* const* d_in, const int* in_sizes, int n_in,
                              void* d_out, int out_size) {
    const float* x = (const float*)d_in[0];
    float* out = (float*)d_out;
    float* scratch = nullptr;
    cudaGetSymbolAddress((void**)&scratch, g_scratch);

    dim3 block(32, 8);
    dim3 grid(NZ / 128, NY / 8);   // 8 x 128 = 1024 blocks

    const float* src = x;
    for (int it = 0; it < NITER; ++it) {
        float* dst = (it & 1) ? out : scratch;  // iter 9 lands in d_out
        diff_step<<<grid, block>>>(src, dst);
        src = dst;
    }
}

// round 6
// speedup vs baseline: 1.4953x; 1.0574x over previous
#include <cuda_runtime.h>
#include <cstdint>

// Diffusion_38929583571393: 10 iters of x += 0.05*(grad_x+grad_y+grad_z) on a
// (64,1024,1024) fp32 volume, torch.gradient semantics.
//
// R6: cp.async smem ring (R5, 105us/launch, L1=65% top util) + two changes:
//  - center planes register-rotated (cm/cc in regs; only new centers LDS'd)
//  - 2 planes per wait_group/__syncthreads (LDS/plane -36%, barriers halved)

#define NX 64
#define NY 1024
#define NZ 1024
#define SX (NY * NZ)
#define SY (NZ)
#define COEFF 0.05f
#define NITER 10

#define S 8                   // ring stages
#define ROWP 136              // floats per staged row (z0-4 .. z0+131)
#define STAGE_F (10 * ROWP)   // 10 rows (y0-1 .. y0+8)
#define NOPS 340              // 10 rows * 34 x 16B chunks per stage

__device__ float g_scratch[(size_t)NX * NY * NZ];

__device__ __forceinline__ void cpa16(uint32_t s, const float* __restrict__ g) {
    asm volatile("cp.async.cg.shared.global [%0], [%1], 16;" :: "r"(s), "l"(g));
}
__device__ __forceinline__ void cp_commit() {
    asm volatile("cp.async.commit_group;" ::: "memory");
}
__device__ __forceinline__ void cp_wait3() {
    asm volatile("cp.async.wait_group 3;" ::: "memory");
}

__global__ __launch_bounds__(256, 4) void diff_step(const float* __restrict__ in,
                                                    float* __restrict__ out) {
    __shared__ float st[S * STAGE_F];   // 43520 B

    const int tx = threadIdx.x;         // 0..31, z direction (float4)
    const int ty = threadIdx.y;         // 0..7,  y direction
    const int tid = ty * 32 + tx;
    const int z0 = blockIdx.x * 128;
    const int y0 = blockIdx.y * 8;

    const bool y_lo = (y0 == 0 && ty == 0);
    const bool y_hi = (y0 + 8 == NY && ty == 7);
    const bool z_lo = (z0 == 0 && tx == 0);
    const bool z_hi = (z0 + 128 == NZ && tx == 31);

    // Stage-fill op map: op o -> row o/34, chunk o%34. Threads 0..83 do two
    // ops. Out-of-range halo addresses are CLAMPED (loaded but never read by
    // the boundary branches), keeping every cp.async unpredicated & in-bounds.
    int gA, sA, gB = -1, sB = 0;
    {
        int o = tid;
        int ro = o / 34, co = o - ro * 34;
        int gy = min(max(y0 - 1 + ro, 0), NY - 1);
        int gz = min(max(z0 - 4 + 4 * co, 0), NZ - 4);
        gA = gy * SY + gz;
        sA = ro * ROWP + 4 * co;
        o = tid + 256;
        if (o < NOPS) {
            ro = o / 34; co = o - ro * 34;
            gy = min(max(y0 - 1 + ro, 0), NY - 1);
            gz = min(max(z0 - 4 + 4 * co, 0), NZ - 4);
            gB = gy * SY + gz;
            sB = ro * ROWP + 4 * co;
        }
    }

    const uint32_t sbase = (uint32_t)__cvta_generic_to_shared(st);

    // Prologue: issue planes 0..5 (6 groups in flight).
    #pragma unroll
    for (int p = 0; p < 6; ++p) {
        const uint32_t sl = sbase + (uint32_t)(p * STAGE_F * 4);
        const float* gp = in + (size_t)p * SX;
        cpa16(sl + (uint32_t)sA * 4, gp + gA);
        if (gB >= 0) cpa16(sl + (uint32_t)sB * 4, gp + gB);
        cp_commit();
    }

    const int coff = (1 + ty) * ROWP + 4 + 4 * tx;   // center offset in a stage
    const unsigned obase = (unsigned)(y0 + ty) * SY + (unsigned)(z0 + 4 * tx);

    float4 cm = make_float4(0.f, 0.f, 0.f, 0.f);   // plane x-1 (unused at x=0)
    float4 cc = make_float4(0.f, 0.f, 0.f, 0.f);   // plane x (loaded at t=0)

    #pragma unroll 1
    for (int t = 0; t < NX / 2; ++t) {
        const int x = 2 * t;
        cp_wait3();            // planes <= x+2 complete (<=3 groups pending)
        __syncthreads();       // make all threads' staged data visible

        const float* s0 = st + ((x) & 7) * STAGE_F + coff;       // plane x
        const float* s1 = st + ((x + 1) & 7) * STAGE_F + coff;   // plane x+1
        const float* s2 = st + ((x + 2) & 7) * STAGE_F + coff;   // plane x+2

        if (t == 0) cc = *(const float4*)s0;
        const float4 c1 = *(const float4*)s1;
        const float4 c2 = *(const float4*)s2;   // stale at t=31; never used

        // ================= plane x (even; never NX-1) =================
        {
            const float4 ym = *(const float4*)(s0 - ROWP);
            const float4 yp = *(const float4*)(s0 + ROWP);
            const float zl = s0[-1];
            const float zr = s0[4];

            float4 gx;
            if (x == 0) {
                gx.x = c1.x - cc.x; gx.y = c1.y - cc.y;
                gx.z = c1.z - cc.z; gx.w = c1.w - cc.w;
            } else {
                gx.x = 0.5f * (c1.x - cm.x); gx.y = 0.5f * (c1.y - cm.y);
                gx.z = 0.5f * (c1.z - cm.z); gx.w = 0.5f * (c1.w - cm.w);
            }

            float4 gy;
            if (y_lo) {
                gy.x = yp.x - cc.x; gy.y = yp.y - cc.y;
                gy.z = yp.z - cc.z; gy.w = yp.w - cc.w;
            } else if (y_hi) {
                gy.x = cc.x - ym.x; gy.y = cc.y - ym.y;
                gy.z = cc.z - ym.z; gy.w = cc.w - ym.w;
            } else {
                gy.x = 0.5f * (yp.x - ym.x); gy.y = 0.5f * (yp.y - ym.y);
                gy.z = 0.5f * (yp.z - ym.z); gy.w = 0.5f * (yp.w - ym.w);
            }

            float4 gz;
            gz.x = z_lo ? (cc.y - cc.x) : 0.5f * (cc.y - zl);
            gz.y = 0.5f * (cc.z - cc.x);
            gz.z = 0.5f * (cc.w - cc.y);
            gz.w = z_hi ? (cc.w - cc.z) : 0.5f * (zr - cc.z);

            float4 o;
            o.x = fmaf(COEFF, gx.x + gy.x + gz.x, cc.x);
            o.y = fmaf(COEFF, gx.y + gy.y + gz.y, cc.y);
            o.z = fmaf(COEFF, gx.z + gy.z + gz.z, cc.z);
            o.w = fmaf(COEFF, gx.w + gy.w + gz.w, cc.w);
            *reinterpret_cast<float4*>(out + (size_t)x * SX + obase) = o;
        }

        // ================= plane x+1 (odd; NX-1 only at t=31) =================
        {
            const float4 ym = *(const float4*)(s1 - ROWP);
            const float4 yp = *(const float4*)(s1 + ROWP);
            const float zl = s1[-1];
            const float zr = s1[4];

            float4 gx;
            if (x + 1 == NX - 1) {
                gx.x = c1.x - cc.x; gx.y = c1.y - cc.y;
                gx.z = c1.z - cc.z; gx.w = c1.w - cc.w;
            } else {
                gx.x = 0.5f * (c2.x - cc.x); gx.y = 0.5f * (c2.y - cc.y);
                gx.z = 0.5f * (c2.z - cc.z); gx.w = 0.5f * (c2.w - cc.w);
            }

            float4 gy;
            if (y_lo) {
                gy.x = yp.x - c1.x; gy.y = yp.y - c1.y;
                gy.z = yp.z - c1.z; gy.w = yp.w - c1.w;
            } else if (y_hi) {
                gy.x = c1.x - ym.x; gy.y = c1.y - ym.y;
                gy.z = c1.z - ym.z; gy.w = c1.w - ym.w;
            } else {
                gy.x = 0.5f * (yp.x - ym.x); gy.y = 0.5f * (yp.y - ym.y);
                gy.z = 0.5f * (yp.z - ym.z); gy.w = 0.5f * (yp.w - ym.w);
            }

            float4 gz;
            gz.x = z_lo ? (c1.y - c1.x) : 0.5f * (c1.y - zl);
            gz.y = 0.5f * (c1.z - c1.x);
            gz.z = 0.5f * (c1.w - c1.y);
            gz.w = z_hi ? (c1.w - c1.z) : 0.5f * (zr - c1.z);

            float4 o;
            o.x = fmaf(COEFF, gx.x + gy.x + gz.x, c1.x);
            o.y = fmaf(COEFF, gx.y + gy.y + gz.y, c1.y);
            o.z = fmaf(COEFF, gx.z + gy.z + gz.z, c1.z);
            o.w = fmaf(COEFF, gx.w + gy.w + gz.w, c1.w);
            *reinterpret_cast<float4*>(out + (size_t)(x + 1) * SX + obase) = o;
        }

        // rotate center registers
        cm = c1;
        cc = c2;

        // Prefetch planes x+6 and x+7 into slots of planes x-2 / x-1 (last
        // read in the previous pair-iteration, before this iter's barrier).
        #pragma unroll
        for (int k = 0; k < 2; ++k) {
            const int p = x + 6 + k;
            if (p < NX) {
                const uint32_t sl = sbase + (uint32_t)((p & 7) * STAGE_F * 4);
                const float* gp = in + (size_t)p * SX;
                cpa16(sl + (uint32_t)sA * 4, gp + gA);
                if (gB >= 0) cpa16(sl + (uint32_t)sB * 4, gp + gB);
            }
            cp_commit();   // commit even when empty: keeps group count fixed
        }
    }
}

extern "C" void kernel_launch(void* const* d_in, const int* in_sizes, int n_in,
                              void* d_out, int out_size) {
    const float* x = (const float*)d_in[0];
    float* out = (float*)d_out;
    float* scratch = nullptr;
    cudaGetSymbolAddress((void**)&scratch, g_scratch);

    dim3 block(32, 8);
    dim3 grid(NZ / 128, NY / 8);   // 8 x 128 = 1024 blocks

    const float* src = x;
    for (int it = 0; it < NITER; ++it) {
        float* dst = (it & 1) ? out : scratch;  // iter 9 lands in d_out
        diff_step<<<grid, block>>>(src, dst);
        src = dst;
    }
}

// round 15
// speedup vs baseline: 1.5963x; 1.0675x over previous
#include <cuda_runtime.h>
#include <cstdint>

// Diffusion_38929583571393: 10 iters of x += 0.05*(grad_x+grad_y+grad_z),
// (64,1024,1024) fp32, torch.gradient semantics.
//
// R7-R15: TEMPORAL FUSION — 2 diffusion iterations per kernel pass (5 launches).
// cp.async stages src planes with 2-halo (12 rows x 136 cols) in a 6-deep
// ring; iter-1 computed on a 1-halo tile (10x136) into a 2-stage smem ring
// (core 1:1 per thread + 84 halo chunk-ops on threads 0..83); iter-2 computed
// for the 8x128 core and written to gmem. src & iter-1 centers are
// register-rotated so both x-gradients cost zero LDS.

#define NX 64
#define NY 1024
#define NZ 1024
#define SXl (NY * NZ)
#define COEFF 0.05f
#define NLAUNCH 5        // 5 fused launches = 10 iterations

#define DS 6             // src ring depth (planes)
#define ROWP 136         // staged row: cols z0-4 .. z0+131
#define SROWS 12         // src rows y0-2 .. y0+9
#define SSTAGE (SROWS * ROWP)   // 1632 floats
#define IROWS 10         // iter1 rows y0-1 .. y0+8
#define ISTAGE (IROWS * ROWP)   // 1360 floats
#define SMEM_BYTES ((DS * SSTAGE + 2 * ISTAGE) * 4)   // 50048 B

__device__ float g_scratch[(size_t)NX * NY * NZ];

__device__ __forceinline__ float4 ld4(const float* __restrict__ p) {
    return *reinterpret_cast<const float4*>(p);
}
__device__ __forceinline__ void cpa16(uint32_t s, const float* __restrict__ g) {
    asm volatile("cp.async.cg.shared.global [%0], [%1], 16;" :: "r"(s), "l"(g));
}
__device__ __forceinline__ void cp_commit() {
    asm volatile("cp.async.commit_group;" ::: "memory");
}
__device__ __forceinline__ void cp_wait2() {
    asm volatile("cp.async.wait_group 2;" ::: "memory");
}
__device__ __forceinline__ void cp_wait3() {
    asm volatile("cp.async.wait_group 3;" ::: "memory");
}

// One diffusion update for a float4 chunk.  p = plane index for the x-axis
// one-sided branches; ylo/yhi/zlo/zhi = global-boundary flags (zlo applies to
// element 0, zhi to element 3).
__device__ __forceinline__ float4 diff_val(
    float4 xm, float4 cc, float4 xp, float4 ym, float4 yp,
    float zl, float zr, int p, bool ylo, bool yhi, bool zlo, bool zhi)
{
    float4 gx;
    if (p == 0) {
        gx.x = xp.x - cc.x; gx.y = xp.y - cc.y;
        gx.z = xp.z - cc.z; gx.w = xp.w - cc.w;
    } else if (p == NX - 1) {
        gx.x = cc.x - xm.x; gx.y = cc.y - xm.y;
        gx.z = cc.z - xm.z; gx.w = cc.w - xm.w;
    } else {
        gx.x = 0.5f * (xp.x - xm.x); gx.y = 0.5f * (xp.y - xm.y);
        gx.z = 0.5f * (xp.z - xm.z); gx.w = 0.5f * (xp.w - xm.w);
    }
    float4 gy;
    if (ylo) {
        gy.x = yp.x - cc.x; gy.y = yp.y - cc.y;
        gy.z = yp.z - cc.z; gy.w = yp.w - cc.w;
    } else if (yhi) {
        gy.x = cc.x - ym.x; gy.y = cc.y - ym.y;
        gy.z = cc.z - ym.z; gy.w = cc.w - ym.w;
    } else {
        gy.x = 0.5f * (yp.x - ym.x); gy.y = 0.5f * (yp.y - ym.y);
        gy.z = 0.5f * (yp.z - ym.z); gy.w = 0.5f * (yp.w - ym.w);
    }
    float4 gz;
    gz.x = zlo ? (cc.y - cc.x) : 0.5f * (cc.y - zl);
    gz.y = 0.5f * (cc.z - cc.x);
    gz.z = 0.5f * (cc.w - cc.y);
    gz.w = zhi ? (cc.w - cc.z) : 0.5f * (zr - cc.z);

    float4 o;
    o.x = fmaf(COEFF, gx.x + gy.x + gz.x, cc.x);
    o.y = fmaf(COEFF, gx.y + gy.y + gz.y, cc.y);
    o.z = fmaf(COEFF, gx.z + gy.z + gz.z, cc.z);
    o.w = fmaf(COEFF, gx.w + gy.w + gz.w, cc.w);
    return o;
}

__global__ __launch_bounds__(256, 3) void diff2(const float* __restrict__ in,
                                                float* __restrict__ out) {
    extern __shared__ float sm[];
    float* s_src = sm;                    // DS * SSTAGE
    float* s_i1  = sm + DS * SSTAGE;      // 2 * ISTAGE

    const int tx = threadIdx.x;           // 0..31 (z, float4)
    const int ty = threadIdx.y;           // 0..7  (y)
    const int tid = ty * 32 + tx;
    const int z0 = blockIdx.x * 128;
    const int y0 = blockIdx.y * 8;

    // core global-boundary flags
    const bool y_lo = (y0 == 0 && ty == 0);
    const bool y_hi = (y0 + 8 == NY && ty == 7);
    const bool z_lo = (z0 == 0 && tx == 0);
    const bool z_hi = (z0 + 128 == NZ && tx == 31);

    // src stage-fill map: 408 ops = 12 rows x 34 chunks; thread t does op t
    // and (t+256 if t<152). Halo addresses clamped (garbage cells are only
    // read on select paths that discard them).
    int gA, sA, gB = 0, sB = 0;
    {
        int ro = tid / 34, co = tid - ro * 34;
        int gy = min(max(y0 - 2 + ro, 0), NY - 1);
        int gz = min(max(z0 - 4 + 4 * co, 0), NZ - 4);
        gA = gy * NZ + gz;
        sA = ro * ROWP + 4 * co;
        if (tid < 152) {
            int o = tid + 256;
            ro = o / 34; co = o - ro * 34;
            gy = min(max(y0 - 2 + ro, 0), NY - 1);
            gz = min(max(z0 - 4 + 4 * co, 0), NZ - 4);
            gB = gy * NZ + gz;
            sB = ro * ROWP + 4 * co;
        }
    }

    // iter1 halo op map: 84 ops (rows 0 & 9 full; rows 1..8 chunks 0 & 33)
    int offh = 0, offh1 = 0;
    bool hylo = false, hyhi = false, hzlo = false, hzhi = false;
    if (tid < 84) {
        int r1h, ch;
        if (tid < 34)      { r1h = 0; ch = tid; }
        else if (tid < 68) { r1h = 9; ch = tid - 34; }
        else { int k = tid - 68; r1h = 1 + (k >> 1); ch = (k & 1) ? 33 : 0; }
        offh  = (r1h + 1) * ROWP + 4 * ch;   // src offset
        offh1 = r1h * ROWP + 4 * ch;         // iter1 offset
        int gyh = y0 - 1 + r1h;
        hylo = (gyh == 0);
        hyhi = (gyh == NY - 1);
        hzlo = (z0 == 0 && ch == 1);              // elem0 == global z 0
        hzhi = (z0 + 128 == NZ && ch == 32);      // elem3 == global z 1023
    }

    const uint32_t sb = (uint32_t)__cvta_generic_to_shared(s_src);

    // Prologue: fill src planes 0..4 (5 groups)
    #pragma unroll
    for (int p = 0; p < 5; ++p) {
        const uint32_t sl = sb + (uint32_t)(p * SSTAGE * 4);
        const float* gp = in + (size_t)p * SXl;
        cpa16(sl + (uint32_t)sA * 4, gp + gA);
        if (tid < 152) cpa16(sl + (uint32_t)sB * 4, gp + gB);
        cp_commit();
    }

    const int offc_s = (ty + 2) * ROWP + 4 + 4 * tx;   // src core offset
    const int offc_i = (ty + 1) * ROWP + 4 + 4 * tx;   // iter1 core offset
    const size_t obase = (size_t)(y0 + ty) * NZ + (size_t)(z0 + 4 * tx);

    cp_wait3();            // planes 0,1 complete
    __syncthreads();

    float4 c0 = ld4(s_src + offc_s);                 // src[0] center
    float4 c1v = ld4(s_src + SSTAGE + offc_s);       // src[1] center

    // iter1 plane 0 (one-sided x)
    float4 i1c;
    {
        const float* s0 = s_src;
        float4 ym = ld4(s0 + offc_s - ROWP);
        float4 yp = ld4(s0 + offc_s + ROWP);
        i1c = diff_val(c0, c0, c1v, ym, yp, s0[offc_s - 1], s0[offc_s + 4],
                       0, y_lo, y_hi, z_lo, z_hi);
        *reinterpret_cast<float4*>(s_i1 + offc_i) = i1c;
    }
    if (tid < 84) {
        const float* s0 = s_src;
        float4 cc = ld4(s0 + offh);
        float4 hxp = ld4(s_src + SSTAGE + offh);
        float4 ym = ld4(s0 + offh - ROWP);
        float4 yp = ld4(s0 + offh + ROWP);
        float4 hv = diff_val(cc, cc, hxp, ym, yp, s0[offh - 1], s0[offh + 4],
                             0, hylo, hyhi, hzlo, hzhi);
        *reinterpret_cast<float4*>(s_i1 + offh1) = hv;
    }
    float4 i1m = i1c;   // dummy (unused at x==0)

    #pragma unroll 1
    for (int x = 0; x < NX - 1; ++x) {
        cp_wait2();          // src planes <= x+2 complete
        __syncthreads();     // syncA: staged data visible; i1 stage reuse safe

        const int p = x + 1;                                  // iter1 plane
        const float* sp0 = s_src + (p % DS) * SSTAGE;
        const float* spm = s_src + ((p - 1) % DS) * SSTAGE;
        const int pn = (p + 1 < NX) ? (p + 1) : (NX - 1);
        const float* spp = s_src + (pn % DS) * SSTAGE;

        float4 c2 = ld4(spp + offc_s);   // src[p+1] center (clamped @p=63, unused)

        // core iter1 plane p (centers from regs)
        float4 i1p;
        {
            float4 ym = ld4(sp0 + offc_s - ROWP);
            float4 yp = ld4(sp0 + offc_s + ROWP);
            i1p = diff_val(c0, c1v, c2, ym, yp,
                           sp0[offc_s - 1], sp0[offc_s + 4],
                           p, y_lo, y_hi, z_lo, z_hi);
            *reinterpret_cast<float4*>(s_i1 + (p & 1) * ISTAGE + offc_i) = i1p;
        }
        // halo iter1 plane p
        if (tid < 84) {
            float4 cc = ld4(sp0 + offh);
            float4 hxm = ld4(spm + offh);                       // p >= 1 always
            float4 hxp = (p < NX - 1) ? ld4(spp + offh) : cc;
            float4 ym = ld4(sp0 + offh - ROWP);
            float4 yp = ld4(sp0 + offh + ROWP);
            float4 hv = diff_val(hxm, cc, hxp, ym, yp,
                                 sp0[offh - 1], sp0[offh + 4],
                                 p, hylo, hyhi, hzlo, hzhi);
            *reinterpret_cast<float4*>(s_i1 + (p & 1) * ISTAGE + offh1) = hv;
        }
        __syncthreads();     // syncB: iter1 plane p visible

        // iter2 plane x -> gmem
        {
            const float* t0 = s_i1 + (x & 1) * ISTAGE;
            float4 ym = ld4(t0 + offc_i - ROWP);
            float4 yp = ld4(t0 + offc_i + ROWP);
            float4 o = diff_val(i1m, i1c, i1p, ym, yp,
                                t0[offc_i - 1], t0[offc_i + 4],
                                x, y_lo, y_hi, z_lo, z_hi);
            *reinterpret_cast<float4*>(out + (size_t)x * SXl + obase) = o;
        }

        // rotate register rings
        c0 = c1v; c1v = c2;
        i1m = i1c; i1c = i1p;

        // stream src plane x+5 into slot of plane x-1 (last read before syncB)
        const int q = x + 5;
        if (q < NX) {
            const uint32_t sl = sb + (uint32_t)((q % DS) * SSTAGE * 4);
            const float* gp = in + (size_t)q * SXl;
            cpa16(sl + (uint32_t)sA * 4, gp + gA);
            if (tid < 152) cpa16(sl + (uint32_t)sB * 4, gp + gB);
        }
        cp_commit();         // commit even when empty: fixed group arithmetic
    }

    // epilogue: iter2 plane 63 (one-sided x; iter1[63] in i1c/stage 1)
    {
        const int x = NX - 1;
        const float* t0 = s_i1 + (x & 1) * ISTAGE;
        float4 ym = ld4(t0 + offc_i - ROWP);
        float4 yp = ld4(t0 + offc_i + ROWP);
        float4 o = diff_val(i1m, i1c, i1c, ym, yp,
                            t0[offc_i - 1], t0[offc_i + 4],
                            x, y_lo, y_hi, z_lo, z_hi);
        *reinterpret_cast<float4*>(out + (size_t)x * SXl + obase) = o;
    }
}

extern "C" void kernel_launch(void* const* d_in, const int* in_sizes, int n_in,
                              void* d_out, int out_size) {
    const float* x = (const float*)d_in[0];
    float* out = (float*)d_out;
    float* scratch = nullptr;
    cudaGetSymbolAddress((void**)&scratch, g_scratch);

    cudaFuncSetAttribute(diff2, cudaFuncAttributeMaxDynamicSharedMemorySize,
                         SMEM_BYTES);

    dim3 block(32, 8);
    dim3 grid(NZ / 128, NY / 8);   // 1024 blocks

    // dst sequence: out, scratch, out, scratch, out  -> final lands in d_out
    const float* src = x;
    for (int it = 0; it < NLAUNCH; ++it) {
        float* dst = (it & 1) ? scratch : out;
        diff2<<<grid, block, SMEM_BYTES>>>(src, dst);
        src = dst;
    }
}